// round 6
// baseline (speedup 1.0000x reference)
#include <cuda_runtime.h>

// CVXPolicy_Integrator, persistent tf32-mma, round 6:
// NT=1024 (32 warps, occ 50%), k1 64-col chunks (5 bars/tile),
// k2 de-serialized epilogue (lambert on 1 warp/SMSP), small per-warp tiles.

#define Bq    131072
#define Dq    256
#define Hq    100
#define GRID  148
#define NT    1024
#define NTILES (Bq / 128)   // 1024

#define NP1   104      // padded H
#define SW1   264      // w1t row stride (==8 mod 32)
#define XSW   72       // xs row stride (==8 mod 32), 64 data + 8 pad
#define XBUF  (128 * XSW)
#define SW2   104      // w2t/hs row stride (==8 mod 32, dense)

// hidden activations, tf32 bits, k-PERMUTED columns, [B][104]
__device__ unsigned g_H[(size_t)Bq * NP1];

// ---------------- helpers ----------------
__device__ __forceinline__ unsigned cvt_tf32(float f) {
    unsigned u;
    asm("cvt.rna.tf32.f32 %0, %1;" : "=r"(u) : "f"(f));
    return u;
}
__device__ __forceinline__ void mma_tf32(float* c,
                                         unsigned a0, unsigned a1, unsigned a2, unsigned a3,
                                         unsigned b0, unsigned b1) {
    asm volatile(
        "mma.sync.aligned.m16n8k8.row.col.f32.tf32.tf32.f32 "
        "{%0,%1,%2,%3}, {%4,%5,%6,%7}, {%8,%9}, {%0,%1,%2,%3};"
        : "+f"(c[0]), "+f"(c[1]), "+f"(c[2]), "+f"(c[3])
        : "r"(a0), "r"(a1), "r"(a2), "r"(a3), "r"(b0), "r"(b1));
}
__device__ __forceinline__ void cp_async16(void* sdst, const void* gsrc) {
    unsigned s = (unsigned)__cvta_generic_to_shared(sdst);
    asm volatile("cp.async.cg.shared.global [%0], [%1], 16;" :: "r"(s), "l"(gsrc));
}
#define CP_COMMIT() asm volatile("cp.async.commit_group;")
#define CP_WAIT(n)  asm volatile("cp.async.wait_group %0;" :: "n"(n))

// within each 8-block: position(k) = (k&3)<<1 | ((k>>2)&1); pairs {k,k+4} adjacent
__device__ __forceinline__ int permk(int k) {
    return (k & ~7) | ((k & 3) << 1) | ((k >> 2) & 1);
}

__device__ __forceinline__ float tanh_fast(float x) {
    float ax = fabsf(x);
    float e  = __expf(-2.0f * ax);
    float y  = 1.0f + e;
    float r  = __uint_as_float(0x7EF311C3u - __float_as_uint(y));
    r = r * (2.0f - y * r);
    r = r * (2.0f - y * r);
    r = r * (2.0f - y * r);
    float th = fmaf(-2.0f * e, r, 1.0f);
    return copysignf(th, x);
}

// ---------------- kernel 1: h = tanh([z,t]@W1+b1) ----------------
// smem: w1t[104][264] + xs[3][128][72] + b1s[104]  (~216 KB)
#define SMEM1 ((NP1 * SW1 + 3 * XBUF + NP1) * 4)

__global__ void __launch_bounds__(NT, 1)
k1_hidden(const float* __restrict__ z, const float* __restrict__ t,
          const float* __restrict__ W1, const float* __restrict__ b1)
{
    extern __shared__ unsigned sm[];
    unsigned* w1t = sm;
    unsigned* xs  = sm + NP1 * SW1;
    float*    b1s = (float*)(sm + NP1 * SW1 + 3 * XBUF);

    const int tid = threadIdx.x;

    // one-time: W1 transpose + k-rotate (t at k=256) + k-perm
    for (int idx = tid; idx < 257 * Hq; idx += NT) {
        int k = idx / Hq, n = idx - k * Hq;
        int kk = (k == 0) ? 256 : (k - 1);
        w1t[n * SW1 + permk(kk)] = cvt_tf32(W1[idx]);
    }
    for (int idx = tid; idx < NP1 * 7; idx += NT) {
        int n = idx / 7, j = idx - n * 7;
        w1t[n * SW1 + 257 + j] = 0u;
    }
    for (int idx = tid; idx < 4 * SW1; idx += NT) {
        int n = 100 + idx / SW1, j = idx % SW1;
        w1t[n * SW1 + j] = 0u;
    }
    if (tid < NP1) b1s[tid] = (tid < Hq) ? b1[tid] : 0.0f;

    const int warp = tid >> 5, lane = tid & 31;
    const int gid = lane >> 2, tig = lane & 3;
    const int m0  = (warp & 3) * 32;                   // 4 m-groups of 32 rows
    const int ng  = warp >> 2;                         // 8 n-groups over 13 n-tiles
    const int tb  = (ng < 5) ? 2 * ng : (10 + ng - 5); // tile base
    const int ntc = (ng < 5) ? 2 : 1;                  // tile count
    const int mr  = m0 + gid;

    // staging: thread covers row sr, 8-word block sb of each 64-col chunk
    const int sr = tid >> 3, sb = tid & 7;

    // chunks: 4 z-chunks of 64 cols + 1 t-chunk (k=256..263: t + 7 zeros)
    int pt = blockIdx.x, pc = 0;
    float4 rA = make_float4(0.f, 0.f, 0.f, 0.f), rB = rA;

    #define K1_LDG() do {                                                        \
        if (pt < NTILES) {                                                       \
            if (pc < 4) {                                                        \
                const float4* src = (const float4*)z                             \
                    + ((size_t)(pt * 128 + sr)) * 64 + pc * 16 + 2 * sb;         \
                rA = src[0]; rB = src[1];                                        \
            } else {                                                             \
                rA = make_float4(0.f, 0.f, 0.f, 0.f); rB = rA;                   \
                if (sb == 0) rA.x = t[pt * 128 + sr];                            \
            }                                                                    \
        }                                                                        \
        pc++; if (pc == 5) { pc = 0; pt += GRID; }                               \
    } while (0)

    // permuted store: block positions {f0,f4,f1,f5,f2,f6,f3,f7}
    #define K1_STS(bs) do {                                                      \
        unsigned* d = xs + (bs) * XBUF + sr * XSW + sb * 8;                      \
        uint4 u0, u1;                                                            \
        u0.x = cvt_tf32(rA.x); u0.y = cvt_tf32(rB.x);                            \
        u0.z = cvt_tf32(rA.y); u0.w = cvt_tf32(rB.y);                            \
        u1.x = cvt_tf32(rA.z); u1.y = cvt_tf32(rB.z);                            \
        u1.z = cvt_tf32(rA.w); u1.w = cvt_tf32(rB.w);                            \
        *(uint4*)d = u0; *(uint4*)(d + 4) = u1;                                  \
    } while (0)

    K1_LDG();          // chunk 0 -> regs
    K1_STS(0);         // chunk 0 -> buf0
    K1_LDG();          // chunk 1 -> regs
    __syncthreads();

    float acc[2][2][4];
    #pragma unroll
    for (int nt = 0; nt < 2; nt++)
        #pragma unroll
        for (int mf = 0; mf < 2; mf++)
            #pragma unroll
            for (int i = 0; i < 4; i++) acc[nt][mf][i] = 0.0f;

    int bcur = 0;
    for (int tile = blockIdx.x; tile < NTILES; tile += GRID) {
        for (int cc = 0; cc < 5; cc++) {
            int bnext = bcur + 1; if (bnext == 3) bnext = 0;
            K1_STS(bnext);      // stage chunk g+1
            K1_LDG();           // fetch chunk g+2
            __syncthreads();

            const unsigned* xa = xs + bcur * XBUF + mr * XSW + 2 * tig;
            const unsigned* wb = w1t + ((tb * 8 + gid) * SW1) + cc * 64 + 2 * tig;
            const int kst = (cc == 4) ? 1 : 8;
            #pragma unroll
            for (int ks = 0; ks < 8; ks++) {
                if (ks < kst) {
                    const int k0 = ks * 8;
                    uint2 A0 = *(const uint2*)(xa + k0);
                    uint2 A1 = *(const uint2*)(xa + 8 * XSW + k0);
                    uint2 A2 = *(const uint2*)(xa + 16 * XSW + k0);
                    uint2 A3 = *(const uint2*)(xa + 24 * XSW + k0);
                    #pragma unroll
                    for (int nt = 0; nt < 2; nt++) {
                        if (nt < ntc) {
                            uint2 bb = *(const uint2*)(wb + nt * 8 * SW1 + k0);
                            mma_tf32(acc[nt][0], A0.x, A1.x, A0.y, A1.y, bb.x, bb.y);
                            mma_tf32(acc[nt][1], A2.x, A3.x, A2.y, A3.y, bb.x, bb.y);
                        }
                    }
                }
            }
            bcur = bnext;
        }

        // epilogue: bias + tanh + store k-PERMUTED to g_H
        size_t rowb = (size_t)tile * 128 + mr;
        #pragma unroll
        for (int nt = 0; nt < 2; nt++) {
            if (nt < ntc) {
                int col = (tb + nt) * 8 + 2 * tig;
                float bb0 = b1s[col], bb1 = b1s[col + 1];
                int c0 = permk(col), c1 = permk(col + 1);
                #pragma unroll
                for (int mf = 0; mf < 2; mf++) {
                    size_t r0 = rowb + mf * 16;
                    g_H[r0 * NP1 + c0]       = cvt_tf32(tanh_fast(acc[nt][mf][0] + bb0));
                    g_H[r0 * NP1 + c1]       = cvt_tf32(tanh_fast(acc[nt][mf][1] + bb1));
                    g_H[(r0 + 8) * NP1 + c0] = cvt_tf32(tanh_fast(acc[nt][mf][2] + bb0));
                    g_H[(r0 + 8) * NP1 + c1] = cvt_tf32(tanh_fast(acc[nt][mf][3] + bb1));
                    acc[nt][mf][0] = acc[nt][mf][1] = acc[nt][mf][2] = acc[nt][mf][3] = 0.0f;
                }
            }
        }
    }
}

// ---------------- kernel 2 ----------------
// smem: w2t[256][104] + hs[2][128][104] + b2s[256] + r2p[8][128] + scs[128] (~219 KB)
#define HBUF  (128 * SW2)
#define SMEM2 ((Dq * SW2 + 2 * HBUF + Dq + 8 * 128 + 128) * 4)

__device__ __forceinline__ void k2_prefetch(unsigned* hbuf, int tile, int tid) {
    const uint4* src = (const uint4*)(g_H + (size_t)tile * 128 * NP1);
    #pragma unroll
    for (int j = 0; j < 4; j++) {
        int idx = j * NT + tid;
        if (idx < 128 * 26) cp_async16(hbuf + idx * 4, src + idx);
    }
}

__global__ void __launch_bounds__(NT, 1)
k2_policy(const float* __restrict__ W2, const float* __restrict__ b2,
          float* __restrict__ out)
{
    extern __shared__ unsigned sm2[];
    unsigned* w2t = sm2;
    unsigned* hs  = sm2 + Dq * SW2;
    float*    b2s = (float*)(sm2 + Dq * SW2 + 2 * HBUF);
    float*    r2p = b2s + Dq;       // [8][128]
    float*    scs = r2p + 8 * 128;  // [128]

    const int tid = threadIdx.x;

    for (int idx = tid; idx < Hq * Dq; idx += NT) {
        int k = idx >> 8, n = idx & 255;
        w2t[n * SW2 + permk(k)] = cvt_tf32(W2[idx]);
    }
    for (int idx = tid; idx < Dq * 4; idx += NT) {
        int n = idx >> 2, j = idx & 3;
        w2t[n * SW2 + 97 + 2 * j] = 0u;   // pads for k=100..103
    }
    if (tid < Dq) b2s[tid] = b2[tid];

    k2_prefetch(hs, blockIdx.x, tid);
    CP_COMMIT();
    __syncthreads();

    const int warp = tid >> 5, lane = tid & 31;
    const int gid = lane >> 2, tig = lane & 3;
    const int m0 = (warp & 3) * 32;
    const int ng = warp >> 2;          // 0..7
    const int n0 = ng * 32;
    const int mr = m0 + gid;

    int bi = 0;
    for (int tile = blockIdx.x; tile < NTILES; tile += GRID) {
        CP_WAIT(0);
        __syncthreads();
        if (tile + GRID < NTILES) k2_prefetch(hs + (bi ^ 1) * HBUF, tile + GRID, tid);
        CP_COMMIT();

        float acc[4][2][4];
        #pragma unroll
        for (int nt = 0; nt < 4; nt++)
            #pragma unroll
            for (int mf = 0; mf < 2; mf++)
                #pragma unroll
                for (int i = 0; i < 4; i++) acc[nt][mf][i] = 0.0f;

        const unsigned* ha = hs + bi * HBUF + mr * SW2 + 2 * tig;
        const unsigned* wb = w2t + (n0 + gid) * SW2 + 2 * tig;

        #pragma unroll
        for (int ks = 0; ks < 13; ks++) {
            const int k0 = ks * 8;
            uint2 A0 = *(const uint2*)(ha + k0);
            uint2 A1 = *(const uint2*)(ha + 8 * SW2 + k0);
            uint2 A2 = *(const uint2*)(ha + 16 * SW2 + k0);
            uint2 A3 = *(const uint2*)(ha + 24 * SW2 + k0);
            #pragma unroll
            for (int nt = 0; nt < 4; nt++) {
                uint2 bb = *(const uint2*)(wb + nt * 8 * SW2 + k0);
                mma_tf32(acc[nt][0], A0.x, A1.x, A0.y, A1.y, bb.x, bb.y);
                mma_tf32(acc[nt][1], A2.x, A3.x, A2.y, A3.y, bb.x, bb.y);
            }
        }

        // bias + per-row partial ||p||^2 over this warp's 32 cols
        float s0 = 0.f, s1 = 0.f, s2 = 0.f, s3 = 0.f;
        #pragma unroll
        for (int nt = 0; nt < 4; nt++) {
            int col = n0 + nt * 8 + 2 * tig;
            float b0f = b2s[col], b1f = b2s[col + 1];
            acc[nt][0][0] += b0f; acc[nt][0][1] += b1f;
            acc[nt][0][2] += b0f; acc[nt][0][3] += b1f;
            acc[nt][1][0] += b0f; acc[nt][1][1] += b1f;
            acc[nt][1][2] += b0f; acc[nt][1][3] += b1f;
            s0 = fmaf(acc[nt][0][0], acc[nt][0][0], s0); s0 = fmaf(acc[nt][0][1], acc[nt][0][1], s0);
            s1 = fmaf(acc[nt][0][2], acc[nt][0][2], s1); s1 = fmaf(acc[nt][0][3], acc[nt][0][3], s1);
            s2 = fmaf(acc[nt][1][0], acc[nt][1][0], s2); s2 = fmaf(acc[nt][1][1], acc[nt][1][1], s2);
            s3 = fmaf(acc[nt][1][2], acc[nt][1][2], s3); s3 = fmaf(acc[nt][1][3], acc[nt][1][3], s3);
        }
        s0 += __shfl_xor_sync(0xffffffffu, s0, 1); s0 += __shfl_xor_sync(0xffffffffu, s0, 2);
        s1 += __shfl_xor_sync(0xffffffffu, s1, 1); s1 += __shfl_xor_sync(0xffffffffu, s1, 2);
        s2 += __shfl_xor_sync(0xffffffffu, s2, 1); s2 += __shfl_xor_sync(0xffffffffu, s2, 2);
        s3 += __shfl_xor_sync(0xffffffffu, s3, 1); s3 += __shfl_xor_sync(0xffffffffu, s3, 2);
        if (tig == 0) {
            r2p[ng * 128 + mr]      = s0;
            r2p[ng * 128 + mr + 8]  = s1;
            r2p[ng * 128 + mr + 16] = s2;
            r2p[ng * 128 + mr + 24] = s3;
        }
        __syncthreads();

        // Lambert-W Newton: warps 0-3 only (1 per SMSP), one row per lane
        if (warp < 4) {
            int row = warp * 32 + lane;
            float r2 = 0.0f;
            #pragma unroll
            for (int g = 0; g < 8; g++) r2 += r2p[g * 128 + row];
            float w = log1pf(r2);
            #pragma unroll
            for (int it = 0; it < 10; it++) {
                float ew  = __expf(w);
                float num = fmaf(w, ew, -r2);
                float den = fmaf(w, ew, ew);
                w = w - __fdividef(num, den);
            }
            w = fmaxf(w, 0.0f);
            float tn = sqrtf(w);
            float rr = sqrtf(r2);
            float scale = (rr > 1e-12f) ? __fdividef(tn, fmaxf(rr, 1e-12f)) : 1.0f;
            scs[row] = -scale;
        }
        __syncthreads();

        const float sc0 = scs[mr],      sc1 = scs[mr + 8];
        const float sc2 = scs[mr + 16], sc3 = scs[mr + 24];
        const size_t rb = ((size_t)tile * 128 + mr) * Dq;
        #pragma unroll
        for (int nt = 0; nt < 4; nt++) {
            int col = n0 + nt * 8 + 2 * tig;
            *(float2*)&out[rb + col]           = make_float2(sc0 * acc[nt][0][0], sc0 * acc[nt][0][1]);
            *(float2*)&out[rb + 8  * Dq + col] = make_float2(sc1 * acc[nt][0][2], sc1 * acc[nt][0][3]);
            *(float2*)&out[rb + 16 * Dq + col] = make_float2(sc2 * acc[nt][1][0], sc2 * acc[nt][1][1]);
            *(float2*)&out[rb + 24 * Dq + col] = make_float2(sc3 * acc[nt][1][2], sc3 * acc[nt][1][3]);
        }
        bi ^= 1;
    }
}

// ---------------- launch ----------------
extern "C" void kernel_launch(void* const* d_in, const int* in_sizes, int n_in,
                              void* d_out, int out_size)
{
    const float* z  = (const float*)d_in[0];
    const float* t  = (const float*)d_in[1];
    const float* W1 = (const float*)d_in[2];
    const float* b1 = (const float*)d_in[3];
    const float* W2 = (const float*)d_in[4];
    const float* b2 = (const float*)d_in[5];
    float* out = (float*)d_out;

    cudaFuncSetAttribute(k1_hidden, cudaFuncAttributeMaxDynamicSharedMemorySize, SMEM1);
    cudaFuncSetAttribute(k2_policy, cudaFuncAttributeMaxDynamicSharedMemorySize, SMEM2);

    k1_hidden<<<GRID, NT, SMEM1>>>(z, t, W1, b1);
    k2_policy<<<GRID, NT, SMEM2>>>(W2, b2, out);
}